// round 8
// baseline (speedup 1.0000x reference)
#include <cuda_runtime.h>
#include <cuda_bf16.h>

#define M 512
#define NBLK 1024          // 512 row-lines + 512 col-lines
#define MARGIN 0.2f

__device__ float2 g_partials[NBLK];
__device__ int    g_count = 0;     // last-block ticket; reset by the finalizing block

// One pass over P pos values held in registers; NV chunk broadcast via float4.
// Returns sum over valid pos of [ sum_chunk relu(n_j - s_i) ] using the
// max identity: sum relu = sum max(n_j, s_i) - chunk*s_i  (NV pads cancel).
template<int P>
__device__ __forceinline__ float pair_block(const float4* __restrict__ nv4, int nit,
                                            const float* __restrict__ PV,
                                            int slot, int np, float fchunk) {
    float si[P], acc[P];
    #pragma unroll
    for (int p = 0; p < P; p++) { si[p] = PV[slot + 64 * p]; acc[p] = 0.f; }

    #pragma unroll 4
    for (int k = 0; k < nit; k++) {
        float4 v = nv4[k];                   // broadcast LDS.128 (warp-uniform)
        #pragma unroll
        for (int p = 0; p < P; p++) {
            acc[p] += fmaxf(v.x, si[p]);
            acc[p] += fmaxf(v.y, si[p]);
            acc[p] += fmaxf(v.z, si[p]);
            acc[p] += fmaxf(v.w, si[p]);
        }
    }
    float tot = 0.f;
    #pragma unroll
    for (int p = 0; p < P; p++) {
        float c = fmaf(-fchunk, si[p], acc[p]);
        tot += (slot + 64 * p < np) ? c : 0.f;   // select out padded pos
    }
    return tot;
}

__global__ __launch_bounds__(512, 4)
void side_kernel(const float* __restrict__ scores,
                 const int* __restrict__ labels,
                 float* __restrict__ out) {
    __shared__ __align__(16) float NV[M];   // compacted (neg + margin), padded w/ -1e30
    __shared__ __align__(16) float PV[M];   // compacted pos scores, zero-padded to 320
    __shared__ int   warp_pos_cnt[16];
    __shared__ float warp_sums[16];
    __shared__ bool  is_last;

    const int b    = blockIdx.x;
    const int t    = threadIdx.x;
    const int lane = t & 31;
    const int w    = t >> 5;

    // row lines: contiguous; col lines: strided (L2-resident)
    int idx;
    if (b < M) idx = b * M + t;
    else       idx = t * M + (b - M);

    const float s   = scores[idx];
    const bool  pos = (labels[idx] == 1);

    // ---- compaction: ballot + shuffle-scan of per-warp counts ----
    const unsigned bal = __ballot_sync(0xffffffffu, pos);
    const unsigned lt  = (1u << lane) - 1u;
    if (lane == 0) warp_pos_cnt[w] = __popc(bal);
    __syncthreads();

    int c = (lane < 16) ? warp_pos_cnt[lane] : 0;
    #pragma unroll
    for (int o = 1; o < 16; o <<= 1) {
        int n = __shfl_up_sync(0xffffffffu, c, o);
        if (lane >= o) c += n;
    }
    const int np       = __shfl_sync(0xffffffffu, c, 15);
    const int base_pos = (w == 0) ? 0 : __shfl_sync(0xffffffffu, c, w - 1);

    const int nn     = M - np;
    const int nn_pad = (nn + 31) & ~31;      // multiple of 32, <= M

    if (pos) PV[base_pos + __popc(bal & lt)] = s;
    else     NV[(w * 32 - base_pos) + __popc(~bal & lt)] = s + MARGIN;
    // NV pads: max(-1e30, si) == si and the padded count is subtracted -> exact zero.
    if (t < nn_pad - nn) NV[nn + t] = -1e30f;
    // PV pads (zero; selected out in pair_block)
    if (t >= np && t < 320) PV[t] = 0.f;
    __syncthreads();

    // ---- pair loop: ONE pass, P pos per thread in registers ----
    // NV split 8 ways per warp-octet (q = w&7): all 32 lanes of a warp read the
    // SAME float4 -> pure broadcast, zero bank conflicts.
    // 64 pos slots (lane + 32*(w>>3)); P=4 covers np<=256, P=5 covers np<=320.
    const int   q      = w & 7;
    const int   chunk  = nn_pad >> 3;        // multiple of 4
    const int   nit    = chunk >> 2;         // float4 iterations
    const float fchunk = (float)chunk;
    const float4* nv4  = reinterpret_cast<const float4*>(NV + q * chunk);
    const int   slot   = lane + ((w >> 3) << 5);

    float total;
    if (np <= 256) total = pair_block<4>(nv4, nit, PV, slot, np, fchunk);
    else           total = pair_block<5>(nv4, nit, PV, slot, np, fchunk);

    // correctness fallback for np > 320 (never taken for Binom(512,1/2) data)
    for (int i = 320 + slot; i < np; i += 64) {
        const float si = PV[i];
        float a = 0.f;
        for (int k = 0; k < nit; k++) {
            float4 v = nv4[k];
            a += fmaxf(v.x, si) + fmaxf(v.y, si) + fmaxf(v.z, si) + fmaxf(v.w, si);
        }
        total = fmaf(-fchunk, si, total + a);
    }

    // ---- deterministic CTA reduction ----
    #pragma unroll
    for (int o = 16; o > 0; o >>= 1)
        total += __shfl_down_sync(0xffffffffu, total, o);
    if (lane == 0) warp_sums[w] = total;
    __syncthreads();

    if (t < 32) {
        float v = (t < 16) ? warp_sums[t] : 0.f;
        #pragma unroll
        for (int o = 8; o > 0; o >>= 1)
            v += __shfl_down_sync(0xffffffffu, v, o);
        if (t == 0) {
            const bool  valid = (np > 0) && (nn > 0);
            const float cnt   = (float)np * (float)nn;   // exact in fp32
            float2 p;
            p.x = valid ? (v / cnt) : 0.f;
            p.y = valid ? 1.f : 0.f;
            g_partials[b] = p;
            __threadfence();
            int cc = atomicAdd(&g_count, 1);
            is_last = (cc == NBLK - 1);
        }
    }
    __syncthreads();

    // ---- last block: fixed-order global reduction + finalize ----
    if (is_last) {
        float m = 0.f, vv = 0.f;
        #pragma unroll
        for (int i = t; i < NBLK; i += 512) {
            float2 p = g_partials[i];
            m  += p.x;
            vv += p.y;
        }
        #pragma unroll
        for (int o = 16; o > 0; o >>= 1) {
            m  += __shfl_down_sync(0xffffffffu, m, o);
            vv += __shfl_down_sync(0xffffffffu, vv, o);
        }
        __shared__ float sm[16], sv[16];
        if (lane == 0) { sm[w] = m; sv[w] = vv; }
        __syncthreads();
        if (t < 32) {
            m  = (t < 16) ? sm[t] : 0.f;
            vv = (t < 16) ? sv[t] : 0.f;
            #pragma unroll
            for (int o = 8; o > 0; o >>= 1) {
                m  += __shfl_down_sync(0xffffffffu, m, o);
                vv += __shfl_down_sync(0xffffffffu, vv, o);
            }
            if (t == 0) {
                out[0] = m / vv;
                g_count = 0;                    // reset for next graph replay
            }
        }
    }
}

extern "C" void kernel_launch(void* const* d_in, const int* in_sizes, int n_in,
                              void* d_out, int out_size) {
    const float* scores = (const float*)d_in[0];
    const int*   labels = (const int*)d_in[1];
    float* out = (float*)d_out;

    side_kernel<<<NBLK, 512>>>(scores, labels, out);
}

// round 9
// speedup vs baseline: 1.0249x; 1.0249x over previous
#include <cuda_runtime.h>
#include <cuda_bf16.h>

#define M 512
#define NBLK 1024          // 512 row-lines + 512 col-lines
#define MARGIN 0.2f
#define NB 512             // buckets == threads

__device__ float2 g_partials[NBLK];
__device__ int    g_count = 0;     // last-block ticket; reset by the finalizing block

__global__ __launch_bounds__(512, 4)
void side_kernel(const float* __restrict__ scores,
                 const int* __restrict__ labels,
                 float* __restrict__ out) {
    __shared__ int   cnt[NB];      // neg count per bucket (original, kept)
    __shared__ float fsum[NB];     // neg value sum per bucket
    __shared__ int   off[NB];      // exclusive prefix of cnt (scatter base)
    __shared__ int   cursor[NB];   // scatter cursors
    __shared__ float NVS[NB];      // negs grouped by bucket
    __shared__ float sufC[NB];     // count of negs in buckets > t (as float)
    __shared__ float sufS[NB];     // sum   of negs in buckets > t
    __shared__ int   wci[16];
    __shared__ float wcf[16];
    __shared__ float warp_sums[16];
    __shared__ bool  is_last;

    const int b    = blockIdx.x;
    const int t    = threadIdx.x;
    const int lane = t & 31;
    const int w    = t >> 5;

    // row lines: contiguous; col lines: strided (L2-resident)
    int idx;
    if (b < M) idx = b * M + t;
    else       idx = t * M + (b - M);

    const float s   = scores[idx];
    const bool  pos = (labels[idx] == 1);
    const float x   = pos ? s : (s + MARGIN);   // neg values carry the margin

    cnt[t]  = 0;
    fsum[t] = 0.f;
    __syncthreads();

    // monotone bucket: floor((x+8)*32), clamped. floor(a)>floor(b) => a>b,
    // so cross-bucket ordering is exact; same-bucket pairs handled directly.
    int k = __float2int_rd((x + 8.0f) * 32.0f);
    k = max(0, min(NB - 1, k));

    if (!pos) {
        atomicAdd(&cnt[k], 1);
        atomicAdd(&fsum[k], x);
    }
    __syncthreads();

    // ---- block-wide inclusive scan over buckets (thread t owns bucket t) ----
    const int   c0 = cnt[t];
    const float f0 = fsum[t];
    int   c = c0;
    float f = f0;
    #pragma unroll
    for (int o = 1; o < 32; o <<= 1) {
        int   nc = __shfl_up_sync(0xffffffffu, c, o);
        float nf = __shfl_up_sync(0xffffffffu, f, o);
        if (lane >= o) { c += nc; f += nf; }
    }
    if (lane == 31) { wci[w] = c; wcf[w] = f; }
    __syncthreads();

    if (t < 32) {
        int   ci = (t < 16) ? wci[t] : 0;
        float fi = (t < 16) ? wcf[t] : 0.f;
        #pragma unroll
        for (int o = 1; o < 16; o <<= 1) {
            int   nc = __shfl_up_sync(0xffffffffu, ci, o);
            float nf = __shfl_up_sync(0xffffffffu, fi, o);
            if (lane >= o) { ci += nc; fi += nf; }
        }
        if (t < 16) { wci[t] = ci; wcf[t] = fi; }   // inclusive warp totals
    }
    __syncthreads();

    const int   incC = c + ((w > 0) ? wci[w - 1] : 0);
    const float incF = f + ((w > 0) ? wcf[w - 1] : 0.f);
    const int   nn   = wci[15];
    const float totF = wcf[15];

    off[t]    = incC - c0;
    cursor[t] = incC - c0;
    sufC[t]   = (float)(nn - incC);
    sufS[t]   = totF - incF;
    __syncthreads();

    // ---- counting scatter: group negs by bucket ----
    if (!pos) {
        int r = atomicAdd(&cursor[k], 1);
        NVS[r] = x;
    }
    __syncthreads();

    // ---- per-pos evaluation: exact suffix part + same-bucket relu scan ----
    float total = 0.f;
    if (pos) {
        total = fmaf(-sufC[k], s, sufS[k]);     // sum over strictly-higher buckets
        const int j0 = off[k];
        const int j1 = j0 + cnt[k];
        for (int j = j0; j < j1; j++)
            total += fmaxf(NVS[j] - s, 0.f);    // same-bucket pairs, exact relu
    }

    // ---- deterministic CTA reduction ----
    #pragma unroll
    for (int o = 16; o > 0; o >>= 1)
        total += __shfl_down_sync(0xffffffffu, total, o);
    if (lane == 0) warp_sums[w] = total;
    __syncthreads();

    if (t < 32) {
        float v = (t < 16) ? warp_sums[t] : 0.f;
        #pragma unroll
        for (int o = 8; o > 0; o >>= 1)
            v += __shfl_down_sync(0xffffffffu, v, o);
        if (t == 0) {
            const int   np    = M - nn;
            const bool  valid = (np > 0) && (nn > 0);
            const float cntf  = (float)np * (float)nn;   // exact in fp32
            float2 p;
            p.x = valid ? (v / cntf) : 0.f;
            p.y = valid ? 1.f : 0.f;
            g_partials[b] = p;
            __threadfence();
            int cc = atomicAdd(&g_count, 1);
            is_last = (cc == NBLK - 1);
        }
    }
    __syncthreads();

    // ---- last block: fixed-order global reduction + finalize ----
    if (is_last) {
        float m = 0.f, vv = 0.f;
        #pragma unroll
        for (int i = t; i < NBLK; i += 512) {
            float2 p = g_partials[i];
            m  += p.x;
            vv += p.y;
        }
        #pragma unroll
        for (int o = 16; o > 0; o >>= 1) {
            m  += __shfl_down_sync(0xffffffffu, m, o);
            vv += __shfl_down_sync(0xffffffffu, vv, o);
        }
        if (lane == 0) { warp_sums[w] = m; wcf[w] = vv; }
        __syncthreads();
        if (t < 32) {
            m  = (t < 16) ? warp_sums[t] : 0.f;
            vv = (t < 16) ? wcf[t] : 0.f;
            #pragma unroll
            for (int o = 8; o > 0; o >>= 1) {
                m  += __shfl_down_sync(0xffffffffu, m, o);
                vv += __shfl_down_sync(0xffffffffu, vv, o);
            }
            if (t == 0) {
                out[0] = m / vv;
                g_count = 0;                    // reset for next graph replay
            }
        }
    }
}

extern "C" void kernel_launch(void* const* d_in, const int* in_sizes, int n_in,
                              void* d_out, int out_size) {
    const float* scores = (const float*)d_in[0];
    const int*   labels = (const int*)d_in[1];
    float* out = (float*)d_out;

    side_kernel<<<NBLK, 512>>>(scores, labels, out);
}

// round 10
// speedup vs baseline: 1.3400x; 1.3075x over previous
#include <cuda_runtime.h>
#include <cuda_bf16.h>

#define M 512
#define NBLK 1024          // 512 row-lines + 512 col-lines
#define MARGIN 0.2f
#define NT 256             // threads per CTA
#define NB 256             // buckets == threads

__device__ float2 g_partials[NBLK];
__device__ int    g_count = 0;     // last-block ticket; reset by the finalizing block

__global__ __launch_bounds__(NT, 8)
void side_kernel(const float* __restrict__ scores,
                 const int* __restrict__ labels,
                 float* __restrict__ out) {
    __shared__ int   cnt[NB];      // neg count per bucket
    __shared__ float fsum[NB];     // neg value sum per bucket
    __shared__ int   off[NB];      // exclusive prefix of cnt (scatter base)
    __shared__ int   cursor[NB];   // scatter cursors
    __shared__ float NVS[M];       // negs grouped by bucket (up to 512)
    __shared__ float sufC[NB];     // count of negs in buckets > t (as float)
    __shared__ float sufS[NB];     // sum   of negs in buckets > t
    __shared__ int   wci[8];
    __shared__ float wcf[8];
    __shared__ float warp_sums[8];
    __shared__ bool  is_last;

    const int b    = blockIdx.x;
    const int t    = threadIdx.x;
    const int lane = t & 31;
    const int w    = t >> 5;

    // each thread owns elements t and t+256 of the line
    int idx0, idx1;
    if (b < M) { idx0 = b * M + t;       idx1 = idx0 + NT; }
    else       { idx0 = t * M + (b - M); idx1 = idx0 + NT * M; }

    const float s0 = scores[idx0];
    const float s1 = scores[idx1];
    const bool  p0 = (labels[idx0] == 1);
    const bool  p1 = (labels[idx1] == 1);
    const float x0 = p0 ? s0 : (s0 + MARGIN);
    const float x1 = p1 ? s1 : (s1 + MARGIN);

    cnt[t]  = 0;
    fsum[t] = 0.f;
    __syncthreads();

    // monotone bucket: floor((x+8)*16), clamped to [0,255].
    // floor+clamp is monotone: k(a) > k(b) => a > b, so the cross-bucket
    // suffix part is exact; same-bucket pairs are handled by direct relu.
    int k0 = max(0, min(NB - 1, __float2int_rd((x0 + 8.0f) * 16.0f)));
    int k1 = max(0, min(NB - 1, __float2int_rd((x1 + 8.0f) * 16.0f)));

    if (!p0) { atomicAdd(&cnt[k0], 1); atomicAdd(&fsum[k0], x0); }
    if (!p1) { atomicAdd(&cnt[k1], 1); atomicAdd(&fsum[k1], x1); }
    __syncthreads();

    // ---- block-wide inclusive scan over 256 buckets ----
    const int   c0 = cnt[t];
    const float f0 = fsum[t];
    int   c = c0;
    float f = f0;
    #pragma unroll
    for (int o = 1; o < 32; o <<= 1) {
        int   nc = __shfl_up_sync(0xffffffffu, c, o);
        float nf = __shfl_up_sync(0xffffffffu, f, o);
        if (lane >= o) { c += nc; f += nf; }
    }
    if (lane == 31) { wci[w] = c; wcf[w] = f; }
    __syncthreads();

    if (t < 32) {
        int   ci = (t < 8) ? wci[t] : 0;
        float fi = (t < 8) ? wcf[t] : 0.f;
        #pragma unroll
        for (int o = 1; o < 8; o <<= 1) {
            int   nc = __shfl_up_sync(0xffffffffu, ci, o);
            float nf = __shfl_up_sync(0xffffffffu, fi, o);
            if (lane >= o) { ci += nc; fi += nf; }
        }
        if (t < 8) { wci[t] = ci; wcf[t] = fi; }   // inclusive warp totals
    }
    __syncthreads();

    const int   incC = c + ((w > 0) ? wci[w - 1] : 0);
    const float incF = f + ((w > 0) ? wcf[w - 1] : 0.f);
    const int   nn   = wci[7];
    const float totF = wcf[7];

    off[t]    = incC - c0;
    cursor[t] = incC - c0;
    sufC[t]   = (float)(nn - incC);
    sufS[t]   = totF - incF;
    __syncthreads();

    // ---- counting scatter: group negs by bucket ----
    if (!p0) { int r = atomicAdd(&cursor[k0], 1); NVS[r] = x0; }
    if (!p1) { int r = atomicAdd(&cursor[k1], 1); NVS[r] = x1; }
    __syncthreads();

    // ---- per-pos evaluation: exact suffix part + same-bucket relu scan ----
    float total = 0.f;
    if (p0) {
        float a = fmaf(-sufC[k0], s0, sufS[k0]);
        const int j0 = off[k0], j1 = j0 + cnt[k0];
        for (int j = j0; j < j1; j++) a += fmaxf(NVS[j] - s0, 0.f);
        total += a;
    }
    if (p1) {
        float a = fmaf(-sufC[k1], s1, sufS[k1]);
        const int j0 = off[k1], j1 = j0 + cnt[k1];
        for (int j = j0; j < j1; j++) a += fmaxf(NVS[j] - s1, 0.f);
        total += a;
    }

    // ---- deterministic CTA reduction ----
    #pragma unroll
    for (int o = 16; o > 0; o >>= 1)
        total += __shfl_down_sync(0xffffffffu, total, o);
    if (lane == 0) warp_sums[w] = total;
    __syncthreads();

    if (t < 32) {
        float v = (t < 8) ? warp_sums[t] : 0.f;
        #pragma unroll
        for (int o = 4; o > 0; o >>= 1)
            v += __shfl_down_sync(0xffffffffu, v, o);
        if (t == 0) {
            const int   np    = M - nn;
            const bool  valid = (np > 0) && (nn > 0);
            const float cntf  = (float)np * (float)nn;   // exact in fp32
            float2 p;
            p.x = valid ? (v / cntf) : 0.f;
            p.y = valid ? 1.f : 0.f;
            g_partials[b] = p;
            __threadfence();
            int cc = atomicAdd(&g_count, 1);
            is_last = (cc == NBLK - 1);
        }
    }
    __syncthreads();

    // ---- last block: fixed-order global reduction + finalize ----
    if (is_last) {
        float m = 0.f, vv = 0.f;
        #pragma unroll
        for (int i = t; i < NBLK; i += NT) {
            float2 p = g_partials[i];
            m  += p.x;
            vv += p.y;
        }
        #pragma unroll
        for (int o = 16; o > 0; o >>= 1) {
            m  += __shfl_down_sync(0xffffffffu, m, o);
            vv += __shfl_down_sync(0xffffffffu, vv, o);
        }
        if (lane == 0) { warp_sums[w] = m; wcf[w] = vv; }
        __syncthreads();
        if (t < 32) {
            m  = (t < 8) ? warp_sums[t] : 0.f;
            vv = (t < 8) ? wcf[t] : 0.f;
            #pragma unroll
            for (int o = 4; o > 0; o >>= 1) {
                m  += __shfl_down_sync(0xffffffffu, m, o);
                vv += __shfl_down_sync(0xffffffffu, vv, o);
            }
            if (t == 0) {
                out[0] = m / vv;
                g_count = 0;                    // reset for next graph replay
            }
        }
    }
}

extern "C" void kernel_launch(void* const* d_in, const int* in_sizes, int n_in,
                              void* d_out, int out_size) {
    const float* scores = (const float*)d_in[0];
    const int*   labels = (const int*)d_in[1];
    float* out = (float*)d_out;

    side_kernel<<<NBLK, NT>>>(scores, labels, out);
}